// round 9
// baseline (speedup 1.0000x reference)
#include <cuda_runtime.h>

// out = foldl over T slices: s = (1-lam)*s + lam*adj[t], s0 = adj[0]
// Pure HBM streaming: 272 MB @ T=16, N=2048 — information-floor traffic,
// pinned at the sm_103a streaming ceiling (6.3-6.65 TB/s across 8 configs).
// This round: Blackwell 256-bit loads (LDG.E.256) — halves LDG count and
// L1tex wavefront-queue entries per byte. Recurrence form (bit-exact).

template <int T>
__global__ void __launch_bounds__(256)
ema_fold_kernel_v8(const float* __restrict__ adj,
                   const float* __restrict__ lam_p,
                   float4* __restrict__ out,
                   int n8) {
    int i = blockIdx.x * blockDim.x + threadIdx.x;   // index in 8-float units
    if (i >= n8) return;

    const float lam = __ldg(lam_p);
    const float om  = 1.0f - lam;

    const float* base = adj + (size_t)i * 8;
    const size_t slice = (size_t)n8 * 8;             // floats per slice

    float s0, s1, s2, s3, s4, s5, s6, s7;
    asm volatile("ld.global.nc.v8.f32 {%0,%1,%2,%3,%4,%5,%6,%7}, [%8];"
                 : "=f"(s0), "=f"(s1), "=f"(s2), "=f"(s3),
                   "=f"(s4), "=f"(s5), "=f"(s6), "=f"(s7)
                 : "l"(base));

#pragma unroll
    for (int t = 1; t < T; ++t) {
        float v0, v1, v2, v3, v4, v5, v6, v7;
        asm volatile("ld.global.nc.v8.f32 {%0,%1,%2,%3,%4,%5,%6,%7}, [%8];"
                     : "=f"(v0), "=f"(v1), "=f"(v2), "=f"(v3),
                       "=f"(v4), "=f"(v5), "=f"(v6), "=f"(v7)
                     : "l"(base + (size_t)t * slice));
        s0 = fmaf(om, s0, lam * v0);
        s1 = fmaf(om, s1, lam * v1);
        s2 = fmaf(om, s2, lam * v2);
        s3 = fmaf(om, s3, lam * v3);
        s4 = fmaf(om, s4, lam * v4);
        s5 = fmaf(om, s5, lam * v5);
        s6 = fmaf(om, s6, lam * v6);
        s7 = fmaf(om, s7, lam * v7);
    }

    float4* o = out + (size_t)i * 2;
    o[0] = make_float4(s0, s1, s2, s3);
    o[1] = make_float4(s4, s5, s6, s7);
}

// Generic-T fallback (runtime T), float4 path.
__global__ void __launch_bounds__(256, 8)
ema_fold_generic(const float4* __restrict__ adj,
                 const float* __restrict__ lam_p,
                 float4* __restrict__ out,
                 int n4, int T) {
    int i = blockIdx.x * blockDim.x + threadIdx.x;
    if (i >= n4) return;

    const float lam = __ldg(lam_p);
    const float om  = 1.0f - lam;

    const float4* p = adj + i;
    float4 s = p[0];
    for (int t = 1; t < T; ++t) {
        float4 v = p[(size_t)t * (size_t)n4];
        s.x = fmaf(om, s.x, lam * v.x);
        s.y = fmaf(om, s.y, lam * v.y);
        s.z = fmaf(om, s.z, lam * v.z);
        s.w = fmaf(om, s.w, lam * v.w);
    }
    out[i] = s;
}

extern "C" void kernel_launch(void* const* d_in, const int* in_sizes, int n_in,
                              void* d_out, int out_size) {
    const float* adj  = (const float*)d_in[0];
    const float* lamp = (const float*)d_in[1];
    float4*      out  = (float4*)d_out;

    const int total = in_sizes[0];        // T * N * N
    const int T     = total / out_size;   // leading axis length

    const int threads = 256;

    if (T == 16 && (out_size % 8) == 0) {
        const int n8 = out_size / 8;
        const int blocks = (n8 + threads - 1) / threads;
        ema_fold_kernel_v8<16><<<blocks, threads>>>(adj, lamp, out, n8);
    } else {
        const int n4 = out_size / 4;
        const int blocks = (n4 + threads - 1) / threads;
        ema_fold_generic<<<blocks, threads>>>((const float4*)adj, lamp, out, n4, T);
    }
}

// round 10
// speedup vs baseline: 1.0056x; 1.0056x over previous
#include <cuda_runtime.h>

// FINAL KERNEL — RNNGNNLayer fold (EMA over leading axis).
//
// out = foldl over T slices: s = (1-lam)*s + lam*adj[t], s0 = adj[0]
//
// Analysis (9 bench rounds on GB300/sm_103a):
//  * Pure HBM-streaming problem: 272 MB traffic (256 MB read + 16 MB write),
//    already at the information floor — no algorithmic reduction exists.
//  * Measured ceiling: 6.3-6.65 TB/s (82-84% DRAM) across 9 structurally
//    distinct configs (grid/block geometry, occupancy 57-92%, cache hints,
//    MLP front-batching, persistent 1-wave, LDG.128 vs LDG.256). All land
//    within the documented LTS-cap run-to-run variation band; no knob moved
//    throughput. Compute pipes correctly idle (fma ~9%, tensor 0%).
//  * Recurrence form matches the reference scan bit-exactly (rel_err = 0).

template <int T>
__global__ void __launch_bounds__(256, 8)
ema_fold_kernel(const float4* __restrict__ adj,
                const float* __restrict__ lam_p,
                float4* __restrict__ out,
                int n4) {
    int i = blockIdx.x * blockDim.x + threadIdx.x;
    if (i >= n4) return;

    const float lam = __ldg(lam_p);
    const float om  = 1.0f - lam;

    const float4* p = adj + i;
    float4 s = p[0];
#pragma unroll
    for (int t = 1; t < T; ++t) {
        float4 v = p[(size_t)t * (size_t)n4];
        s.x = fmaf(om, s.x, lam * v.x);
        s.y = fmaf(om, s.y, lam * v.y);
        s.z = fmaf(om, s.z, lam * v.z);
        s.w = fmaf(om, s.w, lam * v.w);
    }
    out[i] = s;
}

// Generic-T fallback (runtime T).
__global__ void __launch_bounds__(256, 8)
ema_fold_generic(const float4* __restrict__ adj,
                 const float* __restrict__ lam_p,
                 float4* __restrict__ out,
                 int n4, int T) {
    int i = blockIdx.x * blockDim.x + threadIdx.x;
    if (i >= n4) return;

    const float lam = __ldg(lam_p);
    const float om  = 1.0f - lam;

    const float4* p = adj + i;
    float4 s = p[0];
    for (int t = 1; t < T; ++t) {
        float4 v = p[(size_t)t * (size_t)n4];
        s.x = fmaf(om, s.x, lam * v.x);
        s.y = fmaf(om, s.y, lam * v.y);
        s.z = fmaf(om, s.z, lam * v.z);
        s.w = fmaf(om, s.w, lam * v.w);
    }
    out[i] = s;
}

extern "C" void kernel_launch(void* const* d_in, const int* in_sizes, int n_in,
                              void* d_out, int out_size) {
    const float4* adj  = (const float4*)d_in[0];
    const float*  lamp = (const float*)d_in[1];
    float4*       out  = (float4*)d_out;

    const int total = in_sizes[0];        // T * N * N
    const int T     = total / out_size;   // leading axis length
    const int n4    = out_size / 4;       // float4 elements per slice

    const int threads = 256;
    const int blocks  = (n4 + threads - 1) / threads;

    if (T == 16) {
        ema_fold_kernel<16><<<blocks, threads>>>(adj, lamp, out, n4);
    } else {
        ema_fold_generic<<<blocks, threads>>>(adj, lamp, out, n4, T);
    }
}